// round 8
// baseline (speedup 1.0000x reference)
#include <cuda_runtime.h>
#include <cuda_fp16.h>
#include <cstdint>

// ---------------------------------------------------------------------------
// QuantLinear: out[M,N] = x[M,K] @ dequant(qweight)[K,N] + bias[N]
// M=4096, K=4096, N=11008.  compute_103 PTX => HMMA mma.sync path.
//
// Launch 1: convx  x fp32 -> fp16 (g_Xh [M,K])
// Launch 2: dequant (SMEM-transposed, 32kp x 64n tiles, 6 CTAs/SM)
// Launch 3: GEMM 128x256 CTA tile, BK=64, 3-stage cp.async, 512 thr,
//           warp tile 64x32 (2m x 8n), 1 CTA/SM (16 warps).
// ---------------------------------------------------------------------------

#define M_DIM 4096
#define K_DIM 4096
#define N_DIM 11008

#define BM 128
#define BN 256
#define BK 64
#define STAGES 3
#define KCHUNKS (K_DIM / BK)            // 64
#define A_STAGE_BYTES (BM * 128)        // 16384
#define B_STAGE_BYTES (BN * 128)        // 32768
#define STAGE_BYTES (A_STAGE_BYTES + B_STAGE_BYTES)   // 49152
#define SMEM_TOTAL (STAGES * STAGE_BYTES)             // 147456

#define DQ_SMEM (64 * 33 * 16)          // 33792 B

__device__ __half g_Wt[(size_t)N_DIM * K_DIM];  // [N][K]
__device__ __half g_Xh[(size_t)M_DIM * K_DIM];  // [M][K]

// ---------------------------------------------------------------------------
__device__ __forceinline__ uint32_t smem_u32(const void* p) {
    uint32_t a;
    asm("{ .reg .u64 t; cvta.to.shared.u64 t, %1; cvt.u32.u64 %0, t; }"
        : "=r"(a) : "l"(p));
    return a;
}

#define CP_ASYNC16(smem_addr, gptr) \
    asm volatile("cp.async.cg.shared.global [%0], [%1], 16;" \
        :: "r"(smem_addr), "l"(__cvta_generic_to_global(gptr)) : "memory")

#define CP_COMMIT() asm volatile("cp.async.commit_group;" ::: "memory")
#define CP_WAIT(n)  asm volatile("cp.async.wait_group %0;" :: "n"(n) : "memory")

__device__ __forceinline__ void ldsm_x4(uint32_t& r0, uint32_t& r1,
                                        uint32_t& r2, uint32_t& r3, uint32_t addr) {
    asm volatile("ldmatrix.sync.aligned.m8n8.x4.shared.b16 {%0,%1,%2,%3}, [%4];"
                 : "=r"(r0), "=r"(r1), "=r"(r2), "=r"(r3) : "r"(addr));
}

__device__ __forceinline__ void mma_16816(float* c, const uint32_t* a, const uint32_t* b) {
    asm volatile(
        "mma.sync.aligned.m16n8k16.row.col.f32.f16.f16.f32 "
        "{%0,%1,%2,%3}, {%4,%5,%6,%7}, {%8,%9}, {%0,%1,%2,%3};"
        : "+f"(c[0]), "+f"(c[1]), "+f"(c[2]), "+f"(c[3])
        : "r"(a[0]), "r"(a[1]), "r"(a[2]), "r"(a[3]), "r"(b[0]), "r"(b[1]));
}

// ---------------------------------------------------------------------------
// Launch 1: x fp32 -> fp16
// ---------------------------------------------------------------------------
__global__ void __launch_bounds__(256)
convx_kernel(const float* __restrict__ x) {
    size_t i = ((size_t)blockIdx.x * blockDim.x + threadIdx.x) * 4;
    float4 v = *reinterpret_cast<const float4*>(x + i);
    __half2 a = __floats2half2_rn(v.x, v.y);
    __half2 b = __floats2half2_rn(v.z, v.w);
    uint2 u;
    u.x = *reinterpret_cast<uint32_t*>(&a);
    u.y = *reinterpret_cast<uint32_t*>(&b);
    *reinterpret_cast<uint2*>(&g_Xh[i]) = u;
}

// ---------------------------------------------------------------------------
// Launch 2: dequant with SMEM transpose; tile 32 kp (256 k) x 64 n.
// Reads qw coalesced (consecutive n), writes g_Wt coalesced (consecutive k).
// 33 KB SMEM -> 6 CTAs/SM.
// ---------------------------------------------------------------------------
__global__ void __launch_bounds__(256)
dequant_kernel(const int* __restrict__ qw,
               const float* __restrict__ sc,
               const int* __restrict__ qz) {
    extern __shared__ uint4 ds[];   // [64 n][33 kp] 16B entries
    int kp0 = blockIdx.x * 32;      // 16 blocks
    int n0  = blockIdx.y * 64;      // 172 blocks
    int tid = threadIdx.x;

#pragma unroll
    for (int i = 0; i < 8; i++) {
        int idx = i * 256 + tid;
        int nl = idx & 63, kl = idx >> 6;   // kl 0..31
        int kp = kp0 + kl;
        int n  = n0 + nl;
        int w32 = qw[(size_t)kp * N_DIM + n];
        int g = kp >> 4;
        float s = sc[(size_t)g * N_DIM + n];
        int zw = qz[(size_t)g * (N_DIM / 8) + (n >> 3)];
        int zq = ((zw >> ((n & 7) * 4)) & 15) + 1;
        __half2 h[4];
#pragma unroll
        for (int j = 0; j < 4; j++) {
            float v0 = s * (float)(((w32 >> (8 * j))     & 15) - zq);
            float v1 = s * (float)(((w32 >> (8 * j + 4)) & 15) - zq);
            h[j] = __floats2half2_rn(v0, v1);
        }
        ds[nl * 33 + kl] = *reinterpret_cast<uint4*>(h);
    }
    __syncthreads();
#pragma unroll
    for (int i = 0; i < 8; i++) {
        int idx = i * 256 + tid;
        int nl = idx >> 5, kl = idx & 31;   // nl 0..63
        *reinterpret_cast<uint4*>(
            &g_Wt[(size_t)(n0 + nl) * K_DIM + (size_t)(kp0 + kl) * 8]) =
            ds[nl * 33 + kl];
    }
}

// ---------------------------------------------------------------------------
// Launch 3: GEMM, 512 threads, warp grid 2(m) x 8(n), warp tile 64x32.
// ---------------------------------------------------------------------------
__device__ __forceinline__ void copy_stage(uint32_t dst, int m_base, int n_base,
                                           int k0, int tid) {
    const __half* Ab = g_Xh + (size_t)m_base * K_DIM + k0;
    const __half* Bb = g_Wt + (size_t)n_base * K_DIM + k0;
    // A: 128 rows x 8 x 16B = 1024 chunks -> 2/thread
#pragma unroll
    for (int i = 0; i < 2; i++) {
        int c = tid + i * 512;
        int row = c >> 3, col = (c & 7) * 16;
        uint32_t sw = (uint32_t)(row * 128 + (col ^ ((row & 7) << 4)));
        CP_ASYNC16(dst + sw, (const char*)Ab + (size_t)row * (K_DIM * 2) + col);
    }
    // B: 256 rows -> 4/thread
#pragma unroll
    for (int i = 0; i < 4; i++) {
        int c = tid + i * 512;
        int row = c >> 3, col = (c & 7) * 16;
        uint32_t sw = (uint32_t)(row * 128 + (col ^ ((row & 7) << 4)));
        CP_ASYNC16(dst + A_STAGE_BYTES + sw,
                   (const char*)Bb + (size_t)row * (K_DIM * 2) + col);
    }
}

__global__ void __launch_bounds__(512, 1)
gemm_kernel(const float* __restrict__ bias, float* __restrict__ out) {
    extern __shared__ __align__(1024) char smem[];
    uint32_t sb = smem_u32(smem);

    int tid = threadIdx.x;
    int wid = tid >> 5, lane = tid & 31;
    int warp_m = wid & 1;   // 2 warps along m (64 rows each)
    int warp_n = wid >> 1;  // 8 warps along n (32 cols each)

    int bid = blockIdx.x;
    int tm = bid & 31;          // 32 m-tiles (m-major raster)
    int tn = bid >> 5;          // 43 n-tiles
    int m_base = tm * BM;
    int n_base = tn * BN;

    // prologue: fill STAGES-1 stages
#pragma unroll
    for (int s = 0; s < STAGES - 1; s++) {
        copy_stage(sb + s * STAGE_BYTES, m_base, n_base, s * BK, tid);
        CP_COMMIT();
    }

    float acc[4][4][4];
#pragma unroll
    for (int i = 0; i < 4; i++)
#pragma unroll
        for (int j = 0; j < 4; j++)
#pragma unroll
            for (int c = 0; c < 4; c++) acc[i][j][c] = 0.0f;

    const int a_row0 = warp_m * 64 + (lane & 15);
    const int a_col0 = (lane >> 4) * 16;
    const int b_row0 = warp_n * 32 + ((lane >> 4) << 3) + (lane & 7);
    const int b_col0 = ((lane >> 3) & 1) * 16;

    int stage_r = 0;
    int stage_w = STAGES - 1;

    for (int kt = 0; kt < KCHUNKS; kt++) {
        CP_WAIT(STAGES - 2);
        __syncthreads();

        int nxt = kt + STAGES - 1;
        if (nxt < KCHUNKS) {
            copy_stage(sb + stage_w * STAGE_BYTES, m_base, n_base, nxt * BK, tid);
        }
        CP_COMMIT();
        stage_w = (stage_w + 1 == STAGES) ? 0 : stage_w + 1;

        uint32_t sA = sb + stage_r * STAGE_BYTES;
        uint32_t sB = sA + A_STAGE_BYTES;
        stage_r = (stage_r + 1 == STAGES) ? 0 : stage_r + 1;

#pragma unroll
        for (int k16 = 0; k16 < 4; k16++) {
            uint32_t a[4][4];
#pragma unroll
            for (int mi = 0; mi < 4; mi++) {
                int row = a_row0 + mi * 16;
                int col = a_col0 + k16 * 32;
                uint32_t addr = sA + row * 128 + (col ^ ((row & 7) << 4));
                ldsm_x4(a[mi][0], a[mi][1], a[mi][2], a[mi][3], addr);
            }
            uint32_t b[4][2];
#pragma unroll
            for (int j = 0; j < 2; j++) {
                int row = b_row0 + j * 16;
                int col = b_col0 + k16 * 32;
                uint32_t addr = sB + row * 128 + (col ^ ((row & 7) << 4));
                ldsm_x4(b[2 * j][0], b[2 * j][1], b[2 * j + 1][0], b[2 * j + 1][1], addr);
            }
#pragma unroll
            for (int mi = 0; mi < 4; mi++)
#pragma unroll
                for (int nj = 0; nj < 4; nj++)
                    mma_16816(acc[mi][nj], a[mi], b[nj]);
        }
    }

    // epilogue: bias + store fp32
    const int m0 = m_base + warp_m * 64;
    const int n0 = n_base + warp_n * 32;
#pragma unroll
    for (int mi = 0; mi < 4; mi++) {
#pragma unroll
        for (int nj = 0; nj < 4; nj++) {
            int m = m0 + mi * 16 + (lane >> 2);
            int n = n0 + nj * 8 + (lane & 3) * 2;
            float2 b2 = *reinterpret_cast<const float2*>(bias + n);
            float2 o0, o1;
            o0.x = acc[mi][nj][0] + b2.x;
            o0.y = acc[mi][nj][1] + b2.y;
            o1.x = acc[mi][nj][2] + b2.x;
            o1.y = acc[mi][nj][3] + b2.y;
            *reinterpret_cast<float2*>(out + (size_t)m * N_DIM + n) = o0;
            *reinterpret_cast<float2*>(out + (size_t)(m + 8) * N_DIM + n) = o1;
        }
    }
}

// ---------------------------------------------------------------------------
extern "C" void kernel_launch(void* const* d_in, const int* in_sizes, int n_in,
                              void* d_out, int out_size) {
    const float* x    = (const float*)d_in[0];
    const int*   qw   = (const int*)d_in[1];
    const float* sc   = (const float*)d_in[2];
    const int*   qz   = (const int*)d_in[3];
    // d_in[4] = g_idx (identity k/128 grouping; folded into index math)
    const float* bias = (const float*)d_in[5];
    float* out = (float*)d_out;

    convx_kernel<<<M_DIM * (size_t)K_DIM / 1024, 256>>>(x);

    cudaFuncSetAttribute(dequant_kernel, cudaFuncAttributeMaxDynamicSharedMemorySize,
                         DQ_SMEM);
    dequant_kernel<<<dim3(K_DIM / 8 / 32, N_DIM / 64), 256, DQ_SMEM>>>(qw, sc, qz);

    cudaFuncSetAttribute(gemm_kernel, cudaFuncAttributeMaxDynamicSharedMemorySize,
                         SMEM_TOTAL);
    gemm_kernel<<<(M_DIM / BM) * (N_DIM / BN), 512, SMEM_TOTAL>>>(bias, out);
}

// round 9
// speedup vs baseline: 1.1433x; 1.1433x over previous
#include <cuda_runtime.h>
#include <cuda_fp16.h>
#include <cstdint>

// ---------------------------------------------------------------------------
// QuantLinear: out[M,N] = x[M,K] @ dequant(qweight)[K,N] + bias[N]
// M=4096, K=4096, N=11008.  compute_103 PTX => HMMA mma.sync path.
//
// Launch 1 (prep, fused): blocks [0,16384) convert x fp32->fp16;
//          remaining 2752 blocks dequant 4-bit -> fp16 W^T via SMEM
//          transpose (coalesced qw reads AND g_Wt writes). Runs both
//          halves concurrently on the chip.
// Launch 2 (gemm): 128x128 CTA tile, BK=64, 3-stage cp.async, 256 thr,
//          warp tile 64x32 (2m x 4n), 2 CTAs/SM.  (proven 810us)
// ---------------------------------------------------------------------------

#define M_DIM 4096
#define K_DIM 4096
#define N_DIM 11008

#define BM 128
#define BN 128
#define BK 64
#define STAGES 3
#define KCHUNKS (K_DIM / BK)            // 64
#define A_STAGE_BYTES (BM * 128)        // 16384
#define B_STAGE_BYTES (BN * 128)        // 16384
#define STAGE_BYTES (A_STAGE_BYTES + B_STAGE_BYTES)   // 32768
#define SMEM_TOTAL (STAGES * STAGE_BYTES)             // 98304

#define CONVX_BLOCKS (M_DIM * K_DIM / 1024)           // 16384
#define DQ_KP_BLKS (K_DIM / 8 / 32)                   // 16
#define DQ_N_BLKS (N_DIM / 64)                        // 172
#define DQ_SMEM (64 * 33 * 16)                        // 33792 B

__device__ __half g_Wt[(size_t)N_DIM * K_DIM];  // [N][K]
__device__ __half g_Xh[(size_t)M_DIM * K_DIM];  // [M][K]

// ---------------------------------------------------------------------------
__device__ __forceinline__ uint32_t smem_u32(const void* p) {
    uint32_t a;
    asm("{ .reg .u64 t; cvta.to.shared.u64 t, %1; cvt.u32.u64 %0, t; }"
        : "=r"(a) : "l"(p));
    return a;
}

#define CP_ASYNC16(smem_addr, gptr) \
    asm volatile("cp.async.cg.shared.global [%0], [%1], 16;" \
        :: "r"(smem_addr), "l"(__cvta_generic_to_global(gptr)) : "memory")

#define CP_COMMIT() asm volatile("cp.async.commit_group;" ::: "memory")
#define CP_WAIT(n)  asm volatile("cp.async.wait_group %0;" :: "n"(n) : "memory")

__device__ __forceinline__ void ldsm_x4(uint32_t& r0, uint32_t& r1,
                                        uint32_t& r2, uint32_t& r3, uint32_t addr) {
    asm volatile("ldmatrix.sync.aligned.m8n8.x4.shared.b16 {%0,%1,%2,%3}, [%4];"
                 : "=r"(r0), "=r"(r1), "=r"(r2), "=r"(r3) : "r"(addr));
}

__device__ __forceinline__ void mma_16816(float* c, const uint32_t* a, const uint32_t* b) {
    asm volatile(
        "mma.sync.aligned.m16n8k16.row.col.f32.f16.f16.f32 "
        "{%0,%1,%2,%3}, {%4,%5,%6,%7}, {%8,%9}, {%0,%1,%2,%3};"
        : "+f"(c[0]), "+f"(c[1]), "+f"(c[2]), "+f"(c[3])
        : "r"(a[0]), "r"(a[1]), "r"(a[2]), "r"(a[3]), "r"(b[0]), "r"(b[1]));
}

// ---------------------------------------------------------------------------
// Launch 1: fused prep (convx + transposed dequant).
// ---------------------------------------------------------------------------
__global__ void __launch_bounds__(256)
prep_kernel(const float* __restrict__ x,
            const int* __restrict__ qw,
            const float* __restrict__ sc,
            const int* __restrict__ qz) {
    extern __shared__ uint4 ds[];   // [64 n][33 kp] 16B entries (dequant only)
    int b = blockIdx.x;
    int tid = threadIdx.x;

    if (b < CONVX_BLOCKS) {
        size_t i = ((size_t)b * 256 + tid) * 4;
        float4 v = *reinterpret_cast<const float4*>(x + i);
        __half2 a = __floats2half2_rn(v.x, v.y);
        __half2 c = __floats2half2_rn(v.z, v.w);
        uint2 u;
        u.x = *reinterpret_cast<uint32_t*>(&a);
        u.y = *reinterpret_cast<uint32_t*>(&c);
        *reinterpret_cast<uint2*>(&g_Xh[i]) = u;
        return;
    }

    int db = b - CONVX_BLOCKS;
    int kp0 = (db % DQ_KP_BLKS) * 32;
    int n0  = (db / DQ_KP_BLKS) * 64;

#pragma unroll
    for (int i = 0; i < 8; i++) {
        int idx = i * 256 + tid;
        int nl = idx & 63, kl = idx >> 6;   // kl 0..31
        int kp = kp0 + kl;
        int n  = n0 + nl;
        int w32 = qw[(size_t)kp * N_DIM + n];
        int g = kp >> 4;
        float s = sc[(size_t)g * N_DIM + n];
        int zw = qz[(size_t)g * (N_DIM / 8) + (n >> 3)];
        int zq = ((zw >> ((n & 7) * 4)) & 15) + 1;
        __half2 h[4];
#pragma unroll
        for (int j = 0; j < 4; j++) {
            float v0 = s * (float)(((w32 >> (8 * j))     & 15) - zq);
            float v1 = s * (float)(((w32 >> (8 * j + 4)) & 15) - zq);
            h[j] = __floats2half2_rn(v0, v1);
        }
        ds[nl * 33 + kl] = *reinterpret_cast<uint4*>(h);
    }
    __syncthreads();
#pragma unroll
    for (int i = 0; i < 8; i++) {
        int idx = i * 256 + tid;
        int nl = idx >> 5, kl = idx & 31;   // nl 0..63
        *reinterpret_cast<uint4*>(
            &g_Wt[(size_t)(n0 + nl) * K_DIM + (size_t)(kp0 + kl) * 8]) =
            ds[nl * 33 + kl];
    }
}

// ---------------------------------------------------------------------------
// Launch 2: GEMM (proven R4/R7 structure).
// ---------------------------------------------------------------------------
__device__ __forceinline__ void copy_stage(uint32_t dst, int m_base, int n_base,
                                           int k0, int tid) {
    const __half* Ab = g_Xh + (size_t)m_base * K_DIM + k0;
    const __half* Bb = g_Wt + (size_t)n_base * K_DIM + k0;
#pragma unroll
    for (int i = 0; i < 4; i++) {
        int c = tid + i * 256;
        int row = c >> 3, col = (c & 7) * 16;
        uint32_t sw = (uint32_t)(row * 128 + (col ^ ((row & 7) << 4)));
        CP_ASYNC16(dst + sw, (const char*)Ab + (size_t)row * (K_DIM * 2) + col);
    }
#pragma unroll
    for (int i = 0; i < 4; i++) {
        int c = tid + i * 256;
        int row = c >> 3, col = (c & 7) * 16;
        uint32_t sw = (uint32_t)(row * 128 + (col ^ ((row & 7) << 4)));
        CP_ASYNC16(dst + A_STAGE_BYTES + sw,
                   (const char*)Bb + (size_t)row * (K_DIM * 2) + col);
    }
}

__global__ void __launch_bounds__(256, 2)
gemm_kernel(const float* __restrict__ bias, float* __restrict__ out) {
    extern __shared__ __align__(1024) char smem[];
    uint32_t sb = smem_u32(smem);

    int tid = threadIdx.x;
    int wid = tid >> 5, lane = tid & 31;
    int warp_m = wid & 1;   // 2 warps along m (64 rows each)
    int warp_n = wid >> 1;  // 4 warps along n (32 cols each)

    int bid = blockIdx.x;
    int tm = bid & 31;          // 32 m-tiles (m-major raster)
    int tn = bid >> 5;          // 86 n-tiles
    int m_base = tm * BM;
    int n_base = tn * BN;

    // prologue: fill STAGES-1 stages
#pragma unroll
    for (int s = 0; s < STAGES - 1; s++) {
        copy_stage(sb + s * STAGE_BYTES, m_base, n_base, s * BK, tid);
        CP_COMMIT();
    }

    float acc[4][4][4];
#pragma unroll
    for (int i = 0; i < 4; i++)
#pragma unroll
        for (int j = 0; j < 4; j++)
#pragma unroll
            for (int c = 0; c < 4; c++) acc[i][j][c] = 0.0f;

    const int a_row0 = warp_m * 64 + (lane & 15);
    const int a_col0 = (lane >> 4) * 16;
    const int b_row0 = warp_n * 32 + ((lane >> 4) << 3) + (lane & 7);
    const int b_col0 = ((lane >> 3) & 1) * 16;

    int stage_r = 0;
    int stage_w = STAGES - 1;

    for (int kt = 0; kt < KCHUNKS; kt++) {
        CP_WAIT(STAGES - 2);
        __syncthreads();

        int nxt = kt + STAGES - 1;
        if (nxt < KCHUNKS) {
            copy_stage(sb + stage_w * STAGE_BYTES, m_base, n_base, nxt * BK, tid);
        }
        CP_COMMIT();
        stage_w = (stage_w + 1 == STAGES) ? 0 : stage_w + 1;

        uint32_t sA = sb + stage_r * STAGE_BYTES;
        uint32_t sB = sA + A_STAGE_BYTES;
        stage_r = (stage_r + 1 == STAGES) ? 0 : stage_r + 1;

#pragma unroll
        for (int k16 = 0; k16 < 4; k16++) {
            uint32_t a[4][4];
#pragma unroll
            for (int mi = 0; mi < 4; mi++) {
                int row = a_row0 + mi * 16;
                int col = a_col0 + k16 * 32;
                uint32_t addr = sA + row * 128 + (col ^ ((row & 7) << 4));
                ldsm_x4(a[mi][0], a[mi][1], a[mi][2], a[mi][3], addr);
            }
            uint32_t b[4][2];
#pragma unroll
            for (int j = 0; j < 2; j++) {
                int row = b_row0 + j * 16;
                int col = b_col0 + k16 * 32;
                uint32_t addr = sB + row * 128 + (col ^ ((row & 7) << 4));
                ldsm_x4(b[2 * j][0], b[2 * j][1], b[2 * j + 1][0], b[2 * j + 1][1], addr);
            }
#pragma unroll
            for (int mi = 0; mi < 4; mi++)
#pragma unroll
                for (int nj = 0; nj < 4; nj++)
                    mma_16816(acc[mi][nj], a[mi], b[nj]);
        }
    }

    // epilogue: bias + store fp32
    const int m0 = m_base + warp_m * 64;
    const int n0 = n_base + warp_n * 32;
#pragma unroll
    for (int mi = 0; mi < 4; mi++) {
#pragma unroll
        for (int nj = 0; nj < 4; nj++) {
            int m = m0 + mi * 16 + (lane >> 2);
            int n = n0 + nj * 8 + (lane & 3) * 2;
            float2 b2 = *reinterpret_cast<const float2*>(bias + n);
            float2 o0, o1;
            o0.x = acc[mi][nj][0] + b2.x;
            o0.y = acc[mi][nj][1] + b2.y;
            o1.x = acc[mi][nj][2] + b2.x;
            o1.y = acc[mi][nj][3] + b2.y;
            *reinterpret_cast<float2*>(out + (size_t)m * N_DIM + n) = o0;
            *reinterpret_cast<float2*>(out + (size_t)(m + 8) * N_DIM + n) = o1;
        }
    }
}

// ---------------------------------------------------------------------------
extern "C" void kernel_launch(void* const* d_in, const int* in_sizes, int n_in,
                              void* d_out, int out_size) {
    const float* x    = (const float*)d_in[0];
    const int*   qw   = (const int*)d_in[1];
    const float* sc   = (const float*)d_in[2];
    const int*   qz   = (const int*)d_in[3];
    // d_in[4] = g_idx (identity k/128 grouping; folded into index math)
    const float* bias = (const float*)d_in[5];
    float* out = (float*)d_out;

    cudaFuncSetAttribute(prep_kernel, cudaFuncAttributeMaxDynamicSharedMemorySize,
                         DQ_SMEM);
    prep_kernel<<<CONVX_BLOCKS + DQ_KP_BLKS * DQ_N_BLKS, 256, DQ_SMEM>>>(
        x, qw, sc, qz);

    cudaFuncSetAttribute(gemm_kernel, cudaFuncAttributeMaxDynamicSharedMemorySize,
                         SMEM_TOTAL);
    gemm_kernel<<<(M_DIM / BM) * (N_DIM / BN), 256, SMEM_TOTAL>>>(bias, out);
}

// round 10
// speedup vs baseline: 1.2024x; 1.0516x over previous
#include <cuda_runtime.h>
#include <cuda_fp16.h>
#include <cstdint>

// ---------------------------------------------------------------------------
// QuantLinear: out[M,N] = x[M,K] @ dequant(qweight)[K,N] + bias[N]
// M=4096, K=4096, N=11008.  compute_103 PTX => HMMA mma.sync path.
//
// Launch 1 (prep, fused): convx blocks + transposed-dequant blocks.
// Launch 2 (gemm): 128x128 CTA tile, BK=64, 3-stage pipeline, 256 thr,
//          warp tile 64x32 (2m x 4n), 2 CTAs/SM.
//          NEW: full/empty mbarrier ring replaces commit/wait+syncthreads;
//          warps proceed independently (no per-chunk lockstep).
// ---------------------------------------------------------------------------

#define M_DIM 4096
#define K_DIM 4096
#define N_DIM 11008

#define BM 128
#define BN 128
#define BK 64
#define STAGES 3
#define KCHUNKS (K_DIM / BK)            // 64
#define A_STAGE_BYTES (BM * 128)        // 16384
#define B_STAGE_BYTES (BN * 128)        // 16384
#define STAGE_BYTES (A_STAGE_BYTES + B_STAGE_BYTES)   // 32768
#define SMEM_TOTAL (1024 + STAGES * STAGE_BYTES)      // 99328

#define CONVX_BLOCKS (M_DIM * K_DIM / 1024)           // 16384
#define DQ_KP_BLKS (K_DIM / 8 / 32)                   // 16
#define DQ_N_BLKS (N_DIM / 64)                        // 172
#define DQ_SMEM (64 * 33 * 16)                        // 33792 B

__device__ __half g_Wt[(size_t)N_DIM * K_DIM];  // [N][K]
__device__ __half g_Xh[(size_t)M_DIM * K_DIM];  // [M][K]

// ---------------------------------------------------------------------------
__device__ __forceinline__ uint32_t smem_u32(const void* p) {
    uint32_t a;
    asm("{ .reg .u64 t; cvta.to.shared.u64 t, %1; cvt.u32.u64 %0, t; }"
        : "=r"(a) : "l"(p));
    return a;
}

#define CP_ASYNC16(smem_addr, gptr) \
    asm volatile("cp.async.cg.shared.global [%0], [%1], 16;" \
        :: "r"(smem_addr), "l"(__cvta_generic_to_global(gptr)) : "memory")

#define MBARRIER_INIT(addr, cnt) \
    asm volatile("mbarrier.init.shared.b64 [%0], %1;" :: "r"(addr), "r"(cnt) : "memory")

#define CP_ARRIVE_NOINC(addr) \
    asm volatile("cp.async.mbarrier.arrive.noinc.shared.b64 [%0];" \
        :: "r"(addr) : "memory")

#define MBARRIER_ARRIVE(addr) \
    asm volatile("mbarrier.arrive.shared.b64 _, [%0];" :: "r"(addr) : "memory")

__device__ __forceinline__ void mbar_wait(uint32_t mbar, uint32_t phase) {
    asm volatile(
        "{\n\t"
        ".reg .pred P;\n\t"
        "LAB_WAIT_%=:\n\t"
        "mbarrier.try_wait.parity.shared.b64 P, [%0], %1, 0x989680;\n\t"
        "@P bra.uni LAB_DONE_%=;\n\t"
        "bra.uni LAB_WAIT_%=;\n\t"
        "LAB_DONE_%=:\n\t"
        "}"
        :: "r"(mbar), "r"(phase) : "memory");
}

__device__ __forceinline__ void ldsm_x4(uint32_t& r0, uint32_t& r1,
                                        uint32_t& r2, uint32_t& r3, uint32_t addr) {
    asm volatile("ldmatrix.sync.aligned.m8n8.x4.shared.b16 {%0,%1,%2,%3}, [%4];"
                 : "=r"(r0), "=r"(r1), "=r"(r2), "=r"(r3) : "r"(addr));
}

__device__ __forceinline__ void mma_16816(float* c, const uint32_t* a, const uint32_t* b) {
    asm volatile(
        "mma.sync.aligned.m16n8k16.row.col.f32.f16.f16.f32 "
        "{%0,%1,%2,%3}, {%4,%5,%6,%7}, {%8,%9}, {%0,%1,%2,%3};"
        : "+f"(c[0]), "+f"(c[1]), "+f"(c[2]), "+f"(c[3])
        : "r"(a[0]), "r"(a[1]), "r"(a[2]), "r"(a[3]), "r"(b[0]), "r"(b[1]));
}

// ---------------------------------------------------------------------------
// Launch 1: fused prep (convx + transposed dequant).
// ---------------------------------------------------------------------------
__global__ void __launch_bounds__(256)
prep_kernel(const float* __restrict__ x,
            const int* __restrict__ qw,
            const float* __restrict__ sc,
            const int* __restrict__ qz) {
    extern __shared__ uint4 ds[];   // [64 n][33 kp] 16B entries (dequant only)
    int b = blockIdx.x;
    int tid = threadIdx.x;

    if (b < CONVX_BLOCKS) {
        size_t i = ((size_t)b * 256 + tid) * 4;
        float4 v = *reinterpret_cast<const float4*>(x + i);
        __half2 a = __floats2half2_rn(v.x, v.y);
        __half2 c = __floats2half2_rn(v.z, v.w);
        uint2 u;
        u.x = *reinterpret_cast<uint32_t*>(&a);
        u.y = *reinterpret_cast<uint32_t*>(&c);
        *reinterpret_cast<uint2*>(&g_Xh[i]) = u;
        return;
    }

    int db = b - CONVX_BLOCKS;
    int kp0 = (db % DQ_KP_BLKS) * 32;
    int n0  = (db / DQ_KP_BLKS) * 64;

#pragma unroll
    for (int i = 0; i < 8; i++) {
        int idx = i * 256 + tid;
        int nl = idx & 63, kl = idx >> 6;   // kl 0..31
        int kp = kp0 + kl;
        int n  = n0 + nl;
        int w32 = qw[(size_t)kp * N_DIM + n];
        int g = kp >> 4;
        float s = sc[(size_t)g * N_DIM + n];
        int zw = qz[(size_t)g * (N_DIM / 8) + (n >> 3)];
        int zq = ((zw >> ((n & 7) * 4)) & 15) + 1;
        __half2 h[4];
#pragma unroll
        for (int j = 0; j < 4; j++) {
            float v0 = s * (float)(((w32 >> (8 * j))     & 15) - zq);
            float v1 = s * (float)(((w32 >> (8 * j + 4)) & 15) - zq);
            h[j] = __floats2half2_rn(v0, v1);
        }
        ds[nl * 33 + kl] = *reinterpret_cast<uint4*>(h);
    }
    __syncthreads();
#pragma unroll
    for (int i = 0; i < 8; i++) {
        int idx = i * 256 + tid;
        int nl = idx >> 5, kl = idx & 31;   // nl 0..63
        *reinterpret_cast<uint4*>(
            &g_Wt[(size_t)(n0 + nl) * K_DIM + (size_t)(kp0 + kl) * 8]) =
            ds[nl * 33 + kl];
    }
}

// ---------------------------------------------------------------------------
// Launch 2: GEMM with decoupled mbarrier pipeline.
// ---------------------------------------------------------------------------
__device__ __forceinline__ void copy_stage(uint32_t dst, int m_base, int n_base,
                                           int k0, int tid) {
    const __half* Ab = g_Xh + (size_t)m_base * K_DIM + k0;
    const __half* Bb = g_Wt + (size_t)n_base * K_DIM + k0;
#pragma unroll
    for (int i = 0; i < 4; i++) {
        int c = tid + i * 256;
        int row = c >> 3, col = (c & 7) * 16;
        uint32_t sw = (uint32_t)(row * 128 + (col ^ ((row & 7) << 4)));
        CP_ASYNC16(dst + sw, (const char*)Ab + (size_t)row * (K_DIM * 2) + col);
    }
#pragma unroll
    for (int i = 0; i < 4; i++) {
        int c = tid + i * 256;
        int row = c >> 3, col = (c & 7) * 16;
        uint32_t sw = (uint32_t)(row * 128 + (col ^ ((row & 7) << 4)));
        CP_ASYNC16(dst + A_STAGE_BYTES + sw,
                   (const char*)Bb + (size_t)row * (K_DIM * 2) + col);
    }
}

__global__ void __launch_bounds__(256, 2)
gemm_kernel(const float* __restrict__ bias, float* __restrict__ out) {
    extern __shared__ __align__(1024) char smem[];
    uint32_t sb = smem_u32(smem);
    const uint32_t data0 = sb + 1024;
    // barriers: full[s] at sb + s*8 ; empty[s] at sb + 32 + s*8

    int tid = threadIdx.x;
    int wid = tid >> 5, lane = tid & 31;
    int warp_m = wid & 1;   // 2 warps along m (64 rows each)
    int warp_n = wid >> 1;  // 4 warps along n (32 cols each)

    int bid = blockIdx.x;
    int tm = bid & 31;          // 32 m-tiles (m-major raster)
    int tn = bid >> 5;          // 86 n-tiles
    int m_base = tm * BM;
    int n_base = tn * BN;

    if (tid == 0) {
#pragma unroll
        for (int s = 0; s < STAGES; s++) {
            MBARRIER_INIT(sb + s * 8, 256);       // full: one noinc-arrive/thread
            MBARRIER_INIT(sb + 32 + s * 8, 8);    // empty: one arrive/warp
        }
    }
    __syncthreads();

    // prologue: fill all STAGES stages
#pragma unroll
    for (int s = 0; s < STAGES; s++) {
        copy_stage(data0 + s * STAGE_BYTES, m_base, n_base, s * BK, tid);
        CP_ARRIVE_NOINC(sb + s * 8);
    }

    float acc[4][4][4];
#pragma unroll
    for (int i = 0; i < 4; i++)
#pragma unroll
        for (int j = 0; j < 4; j++)
#pragma unroll
            for (int c = 0; c < 4; c++) acc[i][j][c] = 0.0f;

    const int a_row0 = warp_m * 64 + (lane & 15);
    const int a_col0 = (lane >> 4) * 16;
    const int b_row0 = warp_n * 32 + ((lane >> 4) << 3) + (lane & 7);
    const int b_col0 = ((lane >> 3) & 1) * 16;

    int s = 0;           // stage index (ring)
    uint32_t ph = 0;     // parity, flips when s wraps

    for (int kt = 0; kt < KCHUNKS; kt++) {
        mbar_wait(sb + s * 8, ph);   // full[s]

        uint32_t sA = data0 + s * STAGE_BYTES;
        uint32_t sB = sA + A_STAGE_BYTES;

#pragma unroll
        for (int k16 = 0; k16 < 4; k16++) {
            uint32_t a[4][4];
#pragma unroll
            for (int mi = 0; mi < 4; mi++) {
                int row = a_row0 + mi * 16;
                int col = a_col0 + k16 * 32;
                uint32_t addr = sA + row * 128 + (col ^ ((row & 7) << 4));
                ldsm_x4(a[mi][0], a[mi][1], a[mi][2], a[mi][3], addr);
            }
            uint32_t b[4][2];
#pragma unroll
            for (int j = 0; j < 2; j++) {
                int row = b_row0 + j * 16;
                int col = b_col0 + k16 * 32;
                uint32_t addr = sB + row * 128 + (col ^ ((row & 7) << 4));
                ldsm_x4(b[2 * j][0], b[2 * j][1], b[2 * j + 1][0], b[2 * j + 1][1], addr);
            }
            if (k16 == 3 && lane == 0) {
                MBARRIER_ARRIVE(sb + 32 + s * 8);   // empty[s]: all reads done
            }
#pragma unroll
            for (int mi = 0; mi < 4; mi++)
#pragma unroll
                for (int nj = 0; nj < 4; nj++)
                    mma_16816(acc[mi][nj], a[mi], b[nj]);
        }

        // refill stage s for chunk kt+STAGES (WAR wait overlaps our own MMAs)
        if (kt + STAGES < KCHUNKS) {
            mbar_wait(sb + 32 + s * 8, ph);   // empty[s]
            copy_stage(data0 + s * STAGE_BYTES, m_base, n_base,
                       (kt + STAGES) * BK, tid);
            CP_ARRIVE_NOINC(sb + s * 8);
        }

        s++;
        if (s == STAGES) { s = 0; ph ^= 1; }
    }

    // epilogue: bias + store fp32
    const int m0 = m_base + warp_m * 64;
    const int n0 = n_base + warp_n * 32;
#pragma unroll
    for (int mi = 0; mi < 4; mi++) {
#pragma unroll
        for (int nj = 0; nj < 4; nj++) {
            int m = m0 + mi * 16 + (lane >> 2);
            int n = n0 + nj * 8 + (lane & 3) * 2;
            float2 b2 = *reinterpret_cast<const float2*>(bias + n);
            float2 o0, o1;
            o0.x = acc[mi][nj][0] + b2.x;
            o0.y = acc[mi][nj][1] + b2.y;
            o1.x = acc[mi][nj][2] + b2.x;
            o1.y = acc[mi][nj][3] + b2.y;
            *reinterpret_cast<float2*>(out + (size_t)m * N_DIM + n) = o0;
            *reinterpret_cast<float2*>(out + (size_t)(m + 8) * N_DIM + n) = o1;
        }
    }
}

// ---------------------------------------------------------------------------
extern "C" void kernel_launch(void* const* d_in, const int* in_sizes, int n_in,
                              void* d_out, int out_size) {
    const float* x    = (const float*)d_in[0];
    const int*   qw   = (const int*)d_in[1];
    const float* sc   = (const float*)d_in[2];
    const int*   qz   = (const int*)d_in[3];
    // d_in[4] = g_idx (identity k/128 grouping; folded into index math)
    const float* bias = (const float*)d_in[5];
    float* out = (float*)d_out;

    cudaFuncSetAttribute(prep_kernel, cudaFuncAttributeMaxDynamicSharedMemorySize,
                         DQ_SMEM);
    prep_kernel<<<CONVX_BLOCKS + DQ_KP_BLKS * DQ_N_BLKS, 256, DQ_SMEM>>>(
        x, qw, sc, qz);

    cudaFuncSetAttribute(gemm_kernel, cudaFuncAttributeMaxDynamicSharedMemorySize,
                         SMEM_TOTAL);
    gemm_kernel<<<(M_DIM / BM) * (N_DIM / BN), 256, SMEM_TOTAL>>>(bias, out);
}